// round 1
// baseline (speedup 1.0000x reference)
#include <cuda_runtime.h>

#define NN 100000
#define NE 1600000
#define NF 128
#define NH 64
#define NC 16

// ---------------- scratch (static device globals; no allocation) ----------------
__device__ float g_norm_src[NN];            // out-degree -> norm
__device__ float g_norm_dst[NN];            // in-degree  -> norm
__device__ float g_h1[(size_t)NN * NH];     // (x@W1)*norm_src
__device__ float g_agg1[(size_t)NN * NH];   // scatter target layer 1
__device__ float g_h2[(size_t)NN * NC];     // (relu(...)@W2)*norm_src
__device__ float g_agg2[(size_t)NN * NC];   // scatter target layer 2

// ---------------- degree accumulation ----------------
__global__ void k_deg(const int* __restrict__ src, const int* __restrict__ dst) {
    int i = blockIdx.x * blockDim.x + threadIdx.x;
    if (i < NE) {
        atomicAdd(&g_norm_src[src[i]], 1.0f);
        atomicAdd(&g_norm_dst[dst[i]], 1.0f);
    }
}

__global__ void k_norm() {
    int i = blockIdx.x * blockDim.x + threadIdx.x;
    if (i < NN) {
        g_norm_src[i] = rsqrtf(fmaxf(g_norm_src[i], 1.0f));
        g_norm_dst[i] = rsqrtf(fmaxf(g_norm_dst[i], 1.0f));
    }
}

// ---------------- layer-1 GEMM: h1 = (x @ W1) * norm_src ----------------
// Tile: 64 nodes x 64 outputs, K-chunks of 16. 256 threads, each computes 4x4.
__global__ void __launch_bounds__(256) k_gemm1(const float* __restrict__ x,
                                               const float* __restrict__ W1) {
    __shared__ __align__(16) float Xs[16][64];  // [k][node]
    __shared__ __align__(16) float Ws[16][64];  // [k][feat]

    const int n0 = blockIdx.x * 64;
    const int tx = threadIdx.x & 15;   // feat group (4 feats)
    const int ty = threadIdx.x >> 4;   // node group (4 nodes)

    // load indices for X: 64 nodes x 4 float4
    const int ldn = threadIdx.x >> 2;  // 0..63 node_local
    const int ldf = threadIdx.x & 3;   // 0..3 float4 within 16-k chunk
    // load indices for W: 16 rows x 16 float4
    const int wk  = threadIdx.x >> 4;  // 0..15 k row
    const int wf  = threadIdx.x & 15;  // 0..15 float4 within row

    float acc[4][4] = {};

    for (int kc = 0; kc < NF / 16; kc++) {
        __syncthreads();
        // X tile (guard node bound)
        float4 xv = make_float4(0.f, 0.f, 0.f, 0.f);
        int n = n0 + ldn;
        if (n < NN)
            xv = *(const float4*)&x[(size_t)n * NF + kc * 16 + ldf * 4];
        Xs[ldf * 4 + 0][ldn] = xv.x;
        Xs[ldf * 4 + 1][ldn] = xv.y;
        Xs[ldf * 4 + 2][ldn] = xv.z;
        Xs[ldf * 4 + 3][ldn] = xv.w;
        // W tile
        *(float4*)&Ws[wk][wf * 4] = *(const float4*)&W1[(size_t)(kc * 16 + wk) * NH + wf * 4];
        __syncthreads();

        #pragma unroll
        for (int kk = 0; kk < 16; kk++) {
            float4 a = *(const float4*)&Xs[kk][ty * 4];
            float4 b = *(const float4*)&Ws[kk][tx * 4];
            float av[4] = {a.x, a.y, a.z, a.w};
            float bv[4] = {b.x, b.y, b.z, b.w};
            #pragma unroll
            for (int i = 0; i < 4; i++)
                #pragma unroll
                for (int j = 0; j < 4; j++)
                    acc[i][j] += av[i] * bv[j];
        }
    }

    #pragma unroll
    for (int i = 0; i < 4; i++) {
        int n = n0 + ty * 4 + i;
        if (n < NN) {
            float s = g_norm_src[n];
            float4 o = make_float4(acc[i][0] * s, acc[i][1] * s, acc[i][2] * s, acc[i][3] * s);
            *(float4*)&g_h1[(size_t)n * NH + tx * 4] = o;
        }
    }
}

// ---------------- layer-1 scatter: agg1[dst] += h1[src] ----------------
// One thread per (edge, 4-feat chunk); 16 chunks per edge.
__global__ void k_scatter1(const int* __restrict__ src, const int* __restrict__ dst) {
    int idx = blockIdx.x * blockDim.x + threadIdx.x;
    int e = idx >> 4;
    int c = idx & 15;
    if (e < NE) {
        int s = __ldg(&src[e]);
        int d = __ldg(&dst[e]);
        float4 v = *(const float4*)&g_h1[(size_t)s * NH + c * 4];
        float* o = &g_agg1[(size_t)d * NH + c * 4];
        atomicAdd(o + 0, v.x);
        atomicAdd(o + 1, v.y);
        atomicAdd(o + 2, v.z);
        atomicAdd(o + 3, v.w);
    }
}

// ---------------- fused: r = relu(agg1*norm_dst + b1); h2 = (r @ W2) * norm_src ----------------
// 256 threads handle 16 nodes; thread = (node_local, out_class).
__global__ void __launch_bounds__(256) k_hidden(const float* __restrict__ b1,
                                                const float* __restrict__ W2) {
    __shared__ __align__(16) float R[16][NH + 4];   // padded rows (stride 68 breaks bank aliasing)
    __shared__ __align__(16) float W2s[NH * NC];

    const int n0 = blockIdx.x * 16;
    const int tid = threadIdx.x;

    // load W2 (64x16 = 1024 floats = 256 float4)
    *(float4*)&W2s[tid * 4] = *(const float4*)&W2[tid * 4];

    // load + activate 16 rows of agg1 (1024 floats)
    {
        int i = tid * 4;
        int nl = i >> 6;
        int k  = i & 63;
        int n = n0 + nl;
        float4 v = make_float4(0.f, 0.f, 0.f, 0.f);
        if (n < NN) {
            v = *(const float4*)&g_agg1[(size_t)n * NH + k];
            float nd = g_norm_dst[n];
            float4 bb = *(const float4*)&b1[k];
            v.x = fmaxf(fmaf(v.x, nd, bb.x), 0.f);
            v.y = fmaxf(fmaf(v.y, nd, bb.y), 0.f);
            v.z = fmaxf(fmaf(v.z, nd, bb.z), 0.f);
            v.w = fmaxf(fmaf(v.w, nd, bb.w), 0.f);
        }
        R[nl][k + 0] = v.x;
        R[nl][k + 1] = v.y;
        R[nl][k + 2] = v.z;
        R[nl][k + 3] = v.w;
    }
    __syncthreads();

    const int nl = tid >> 4;
    const int cl = tid & 15;
    int n = n0 + nl;
    if (n < NN) {
        float acc = 0.f;
        #pragma unroll
        for (int k = 0; k < NH; k++)
            acc = fmaf(R[nl][k], W2s[k * NC + cl], acc);
        g_h2[(size_t)n * NC + cl] = acc * g_norm_src[n];
    }
}

// ---------------- layer-2 scatter: agg2[dst] += h2[src] ----------------
__global__ void k_scatter2(const int* __restrict__ src, const int* __restrict__ dst) {
    int idx = blockIdx.x * blockDim.x + threadIdx.x;
    int e = idx >> 2;
    int c = idx & 3;
    if (e < NE) {
        int s = __ldg(&src[e]);
        int d = __ldg(&dst[e]);
        float4 v = *(const float4*)&g_h2[(size_t)s * NC + c * 4];
        float* o = &g_agg2[(size_t)d * NC + c * 4];
        atomicAdd(o + 0, v.x);
        atomicAdd(o + 1, v.y);
        atomicAdd(o + 2, v.z);
        atomicAdd(o + 3, v.w);
    }
}

// ---------------- final: out = log_softmax(agg2*norm_dst + b2) ----------------
__global__ void k_final(const float* __restrict__ b2, float* __restrict__ out) {
    int n = blockIdx.x * blockDim.x + threadIdx.x;
    if (n >= NN) return;
    float v[NC];
    float nd = g_norm_dst[n];
    #pragma unroll
    for (int c = 0; c < NC; c += 4) {
        float4 a  = *(const float4*)&g_agg2[(size_t)n * NC + c];
        float4 bb = *(const float4*)&b2[c];
        v[c + 0] = fmaf(a.x, nd, bb.x);
        v[c + 1] = fmaf(a.y, nd, bb.y);
        v[c + 2] = fmaf(a.z, nd, bb.z);
        v[c + 3] = fmaf(a.w, nd, bb.w);
    }
    float m = v[0];
    #pragma unroll
    for (int c = 1; c < NC; c++) m = fmaxf(m, v[c]);
    float s = 0.f;
    #pragma unroll
    for (int c = 0; c < NC; c++) s += __expf(v[c] - m);
    float l = m + __logf(s);
    #pragma unroll
    for (int c = 0; c < NC; c += 4) {
        float4 o = make_float4(v[c] - l, v[c + 1] - l, v[c + 2] - l, v[c + 3] - l);
        *(float4*)&out[(size_t)n * NC + c] = o;
    }
}

// ---------------- launch ----------------
extern "C" void kernel_launch(void* const* d_in, const int* in_sizes, int n_in,
                              void* d_out, int out_size) {
    const float* x   = (const float*)d_in[0];
    const int*   src = (const int*)d_in[1];
    const int*   dst = (const int*)d_in[2];
    const float* W1  = (const float*)d_in[3];
    const float* b1  = (const float*)d_in[4];
    const float* W2  = (const float*)d_in[5];
    const float* b2  = (const float*)d_in[6];
    float* out = (float*)d_out;

    void *pns, *pnd, *pa1, *pa2;
    cudaGetSymbolAddress(&pns, g_norm_src);
    cudaGetSymbolAddress(&pnd, g_norm_dst);
    cudaGetSymbolAddress(&pa1, g_agg1);
    cudaGetSymbolAddress(&pa2, g_agg2);
    cudaMemsetAsync(pns, 0, (size_t)NN * sizeof(float));
    cudaMemsetAsync(pnd, 0, (size_t)NN * sizeof(float));
    cudaMemsetAsync(pa1, 0, (size_t)NN * NH * sizeof(float));
    cudaMemsetAsync(pa2, 0, (size_t)NN * NC * sizeof(float));

    k_deg<<<(NE + 255) / 256, 256>>>(src, dst);
    k_norm<<<(NN + 255) / 256, 256>>>();
    k_gemm1<<<(NN + 63) / 64, 256>>>(x, W1);
    k_scatter1<<<(NE * 16) / 256, 256>>>(src, dst);        // 25.6M threads
    k_hidden<<<(NN + 15) / 16, 256>>>(b1, W2);
    k_scatter2<<<(NE * 4) / 256, 256>>>(src, dst);         // 6.4M threads
    k_final<<<(NN + 255) / 256, 256>>>(b2, out);
}

// round 4
// speedup vs baseline: 1.0691x; 1.0691x over previous
#include <cuda_runtime.h>

#define NN 100000
#define NE 1600000
#define NF 128
#define NH 64
#define NC 16

// ---------------- scratch (static device globals) ----------------
__device__ int   g_ideg[NN];
__device__ int   g_odeg[NN];
__device__ float g_norm_src[NN];
__device__ float g_norm_dst[NN];
__device__ int   g_rowptr[NN + 1];
__device__ int   g_cursor[NN];
__device__ int   g_col[NE];                 // src node per CSR slot
__device__ float g_h1[(size_t)NN * NH];     // (x@W1)*norm_src
__device__ float g_r[(size_t)NN * NH];      // relu(agg1*nd + b1)
__device__ float g_h2[(size_t)NN * NC];     // (r@W2)*norm_src

// ---------------- degree histograms ----------------
__global__ void k_hist(const int* __restrict__ src, const int* __restrict__ dst) {
    int i = blockIdx.x * blockDim.x + threadIdx.x;
    if (i < NE) {
        atomicAdd(&g_odeg[src[i]], 1);
        atomicAdd(&g_ideg[dst[i]], 1);
    }
}

__global__ void k_norm() {
    int i = blockIdx.x * blockDim.x + threadIdx.x;
    if (i < NN) {
        g_norm_src[i] = rsqrtf((float)max(g_odeg[i], 1));
        g_norm_dst[i] = rsqrtf((float)max(g_ideg[i], 1));
    }
}

// ---------------- exclusive scan of in-degrees -> rowptr, cursor ----------------
__global__ void __launch_bounds__(1024) k_scan() {
    __shared__ int sblk[1024];
    const int t = threadIdx.x;
    const int CH = (NN + 1023) / 1024;   // 98
    int lo = t * CH;
    int hi = min(lo + CH, NN);
    if (lo > NN) lo = NN;
    int s = 0;
    for (int i = lo; i < hi; i++) s += g_ideg[i];
    sblk[t] = s;
    __syncthreads();
    for (int off = 1; off < 1024; off <<= 1) {
        int u = (t >= off) ? sblk[t - off] : 0;
        __syncthreads();
        sblk[t] += u;
        __syncthreads();
    }
    int run = (t > 0) ? sblk[t - 1] : 0;
    for (int i = lo; i < hi; i++) {
        g_rowptr[i] = run;
        g_cursor[i] = run;
        run += g_ideg[i];
    }
    if (t == 1023) g_rowptr[NN] = sblk[1023];
}

// ---------------- fill CSR ----------------
__global__ void k_fill(const int* __restrict__ src, const int* __restrict__ dst) {
    int e = blockIdx.x * blockDim.x + threadIdx.x;
    if (e < NE) {
        int d = dst[e];
        int pos = atomicAdd(&g_cursor[d], 1);
        g_col[pos] = src[e];
    }
}

// ---------------- layer-1 GEMM: h1 = (x @ W1) * norm_src ----------------
// Block tile 256 nodes x 64 feats; 256 threads; each thread 8 nodes x 8 feats.
// ty in [0,32) -> 32*8 = 256 nodes (matches tile); tx in [0,8) -> 64 feats.
__global__ void __launch_bounds__(256) k_gemm1(const float* __restrict__ x,
                                               const float* __restrict__ W1) {
    __shared__ __align__(16) float Xs[16][256];  // [k][node]  16KB
    __shared__ __align__(16) float Ws[16][64];   // [k][feat]  4KB

    const int tid = threadIdx.x;
    const int tx = tid & 7;     // feat group (8 feats)
    const int ty = tid >> 3;    // node group (8 nodes), 0..31
    const int n0 = blockIdx.x * 256;

    unsigned long long accp[8][4];
    #pragma unroll
    for (int i = 0; i < 8; i++)
        #pragma unroll
        for (int j = 0; j < 4; j++) accp[i][j] = 0ull;

    for (int kc = 0; kc < NF / 16; kc++) {
        __syncthreads();
        // X tile: 256 nodes x 16 k = 1024 float4 loads over 4 iterations
        #pragma unroll
        for (int it = 0; it < 4; it++) {
            int i = tid + it * 256;          // 0..1023
            int nl = i >> 2, f4 = i & 3;
            int n = n0 + nl;
            float4 v = make_float4(0.f, 0.f, 0.f, 0.f);
            if (n < NN) v = *(const float4*)&x[(size_t)n * NF + kc * 16 + f4 * 4];
            Xs[f4 * 4 + 0][nl] = v.x;
            Xs[f4 * 4 + 1][nl] = v.y;
            Xs[f4 * 4 + 2][nl] = v.z;
            Xs[f4 * 4 + 3][nl] = v.w;
        }
        // W tile: 16 k x 64 feats = 256 float4 loads
        {
            int k = tid >> 4, f4 = tid & 15;
            *(float4*)&Ws[k][f4 * 4] =
                *(const float4*)&W1[(size_t)(kc * 16 + k) * NH + f4 * 4];
        }
        __syncthreads();

        #pragma unroll
        for (int kk = 0; kk < 16; kk++) {
            float4 a0 = *(const float4*)&Xs[kk][ty * 8];
            float4 a1 = *(const float4*)&Xs[kk][ty * 8 + 4];
            ulonglong2 w0 = *(const ulonglong2*)&Ws[kk][tx * 8];
            ulonglong2 w1 = *(const ulonglong2*)&Ws[kk][tx * 8 + 4];
            unsigned long long bp[4] = {w0.x, w0.y, w1.x, w1.y};
            float av[8] = {a0.x, a0.y, a0.z, a0.w, a1.x, a1.y, a1.z, a1.w};
            #pragma unroll
            for (int i = 0; i < 8; i++) {
                unsigned long long ad;
                asm("mov.b64 %0, {%1, %1};" : "=l"(ad) : "f"(av[i]));
                #pragma unroll
                for (int jj = 0; jj < 4; jj++)
                    asm("fma.rn.f32x2 %0, %1, %2, %0;"
                        : "+l"(accp[i][jj]) : "l"(ad), "l"(bp[jj]));
            }
        }
    }

    #pragma unroll
    for (int i = 0; i < 8; i++) {
        int n = n0 + ty * 8 + i;
        if (n < NN) {
            float s = g_norm_src[n];
            float o[8];
            #pragma unroll
            for (int jj = 0; jj < 4; jj++) {
                float lo, hi;
                asm("mov.b64 {%0, %1}, %2;" : "=f"(lo), "=f"(hi) : "l"(accp[i][jj]));
                o[2 * jj] = lo * s;
                o[2 * jj + 1] = hi * s;
            }
            *(float4*)&g_h1[(size_t)n * NH + tx * 8] = make_float4(o[0], o[1], o[2], o[3]);
            *(float4*)&g_h1[(size_t)n * NH + tx * 8 + 4] = make_float4(o[4], o[5], o[6], o[7]);
        }
    }
}

// ---------------- layer-1 gather: r = relu(sum_{e->n} h1[src] * nd + b1) ----------------
// 8 lanes per node, each owns 8 feats (2x float4). 256 threads = 32 nodes.
__global__ void __launch_bounds__(256) k_gather1(const float* __restrict__ b1) {
    const int g = blockIdx.x * 32 + (threadIdx.x >> 3);
    const int lane = threadIdx.x & 7;
    const unsigned gb = (threadIdx.x & 31) & ~7u;
    const unsigned mask = 0xFFu << gb;

    const int s0 = g_rowptr[g];
    const int s1 = g_rowptr[g + 1];
    float acc[8] = {};

    for (int base = s0; base < s1; base += 8) {
        int idx = base + lane;
        int myc = (idx < s1) ? g_col[idx] : 0;
        int m = s1 - base;
        if (m > 8) m = 8;
        for (int j = 0; j < m; j++) {
            int s = __shfl_sync(mask, myc, j, 8);
            const float* p = &g_h1[(size_t)s * NH + lane * 8];
            float4 v0 = *(const float4*)p;
            float4 v1 = *(const float4*)(p + 4);
            acc[0] += v0.x; acc[1] += v0.y; acc[2] += v0.z; acc[3] += v0.w;
            acc[4] += v1.x; acc[5] += v1.y; acc[6] += v1.z; acc[7] += v1.w;
        }
    }

    float nd = g_norm_dst[g];
    float4 bb0 = *(const float4*)&b1[lane * 8];
    float4 bb1 = *(const float4*)&b1[lane * 8 + 4];
    float bv[8] = {bb0.x, bb0.y, bb0.z, bb0.w, bb1.x, bb1.y, bb1.z, bb1.w};
    float r[8];
    #pragma unroll
    for (int q = 0; q < 8; q++) r[q] = fmaxf(fmaf(acc[q], nd, bv[q]), 0.f);
    *(float4*)&g_r[(size_t)g * NH + lane * 8] = make_float4(r[0], r[1], r[2], r[3]);
    *(float4*)&g_r[(size_t)g * NH + lane * 8 + 4] = make_float4(r[4], r[5], r[6], r[7]);
}

// ---------------- hidden GEMM: h2 = (r @ W2) * norm_src ----------------
__global__ void __launch_bounds__(256) k_hidden(const float* __restrict__ W2) {
    __shared__ __align__(16) float R[16][NH + 4];
    __shared__ __align__(16) float W2s[NH * NC];

    const int n0 = blockIdx.x * 16;
    const int tid = threadIdx.x;

    *(float4*)&W2s[tid * 4] = *(const float4*)&W2[tid * 4];
    {
        int i = tid * 4;
        int nl = i >> 6;
        int k = i & 63;
        float4 v = *(const float4*)&g_r[(size_t)(n0 + nl) * NH + k];
        R[nl][k + 0] = v.x;
        R[nl][k + 1] = v.y;
        R[nl][k + 2] = v.z;
        R[nl][k + 3] = v.w;
    }
    __syncthreads();

    const int nl = tid >> 4;
    const int cl = tid & 15;
    const int n = n0 + nl;
    float acc = 0.f;
    #pragma unroll
    for (int k = 0; k < NH; k++)
        acc = fmaf(R[nl][k], W2s[k * NC + cl], acc);
    g_h2[(size_t)n * NC + cl] = acc * g_norm_src[n];
}

// ---------------- layer-2 gather + log_softmax fused ----------------
// 2 lanes per node, each owns 8 classes (2x float4). 256 threads = 128 nodes.
__global__ void __launch_bounds__(256) k_gather2(const float* __restrict__ b2,
                                                 float* __restrict__ out) {
    const int g = blockIdx.x * 128 + (threadIdx.x >> 1);
    const int lane = threadIdx.x & 1;
    const unsigned pb = (threadIdx.x & 31) & ~1u;
    const unsigned mask = 3u << pb;
    if (g >= NN) return;

    const int s0 = g_rowptr[g];
    const int s1 = g_rowptr[g + 1];
    float acc[8] = {};

    for (int base = s0; base < s1; base += 2) {
        int idx = base + lane;
        int myc = (idx < s1) ? g_col[idx] : 0;
        int m = s1 - base;
        if (m > 2) m = 2;
        for (int j = 0; j < m; j++) {
            int s = __shfl_sync(mask, myc, j, 2);
            const float* p = &g_h2[(size_t)s * NC + lane * 8];
            float4 v0 = *(const float4*)p;
            float4 v1 = *(const float4*)(p + 4);
            acc[0] += v0.x; acc[1] += v0.y; acc[2] += v0.z; acc[3] += v0.w;
            acc[4] += v1.x; acc[5] += v1.y; acc[6] += v1.z; acc[7] += v1.w;
        }
    }

    float nd = g_norm_dst[g];
    float4 bb0 = *(const float4*)&b2[lane * 8];
    float4 bb1 = *(const float4*)&b2[lane * 8 + 4];
    float bv[8] = {bb0.x, bb0.y, bb0.z, bb0.w, bb1.x, bb1.y, bb1.z, bb1.w};
    float v[8];
    #pragma unroll
    for (int q = 0; q < 8; q++) v[q] = fmaf(acc[q], nd, bv[q]);

    float mloc = v[0];
    #pragma unroll
    for (int q = 1; q < 8; q++) mloc = fmaxf(mloc, v[q]);
    float mo = __shfl_xor_sync(mask, mloc, 1, 2);
    float mx = fmaxf(mloc, mo);

    float sl = 0.f;
    #pragma unroll
    for (int q = 0; q < 8; q++) sl += __expf(v[q] - mx);
    float so = __shfl_xor_sync(mask, sl, 1, 2);
    float l = mx + __logf(sl + so);

    *(float4*)&out[(size_t)g * NC + lane * 8] =
        make_float4(v[0] - l, v[1] - l, v[2] - l, v[3] - l);
    *(float4*)&out[(size_t)g * NC + lane * 8 + 4] =
        make_float4(v[4] - l, v[5] - l, v[6] - l, v[7] - l);
}

// ---------------- launch ----------------
extern "C" void kernel_launch(void* const* d_in, const int* in_sizes, int n_in,
                              void* d_out, int out_size) {
    const float* x   = (const float*)d_in[0];
    const int*   src = (const int*)d_in[1];
    const int*   dst = (const int*)d_in[2];
    const float* W1  = (const float*)d_in[3];
    const float* b1  = (const float*)d_in[4];
    const float* W2  = (const float*)d_in[5];
    const float* b2  = (const float*)d_in[6];
    float* out = (float*)d_out;

    void *pid, *pod;
    cudaGetSymbolAddress(&pid, g_ideg);
    cudaGetSymbolAddress(&pod, g_odeg);
    cudaMemsetAsync(pid, 0, (size_t)NN * sizeof(int));
    cudaMemsetAsync(pod, 0, (size_t)NN * sizeof(int));

    k_hist<<<(NE + 255) / 256, 256>>>(src, dst);
    k_norm<<<(NN + 255) / 256, 256>>>();
    k_scan<<<1, 1024>>>();
    k_fill<<<(NE + 255) / 256, 256>>>(src, dst);
    k_gemm1<<<(NN + 255) / 256, 256>>>(x, W1);
    k_gather1<<<NN / 32, 256>>>(b1);
    k_hidden<<<NN / 16, 256>>>(W2);
    k_gather2<<<(NN + 127) / 128, 256>>>(b2, out);
}

// round 5
// speedup vs baseline: 1.1078x; 1.0362x over previous
#include <cuda_runtime.h>

#define NN 100000
#define NE 1600000
#define NF 128
#define NH 64
#define NC 16

// ---------------- scratch (static device globals) ----------------
__device__ int   g_deg[2 * NN];             // [0,NN): out-degree, [NN,2NN): in-degree
__device__ int   g_rowptr[NN + 1];
__device__ int   g_cursor[NN];
__device__ int   g_col[NE];                 // src node per CSR slot
__device__ float g_h1[(size_t)NN * NH];     // (x@W1)*norm_src
__device__ float g_r[(size_t)NN * NH];      // relu(agg1*nd + b1)
__device__ float g_h2[(size_t)NN * NC];     // (r@W2)*norm_src

#define ADD2(acc, v) asm("add.rn.f32x2 %0, %0, %1;" : "+l"(acc) : "l"(v))

// ---------------- degree histograms ----------------
__global__ void k_hist(const int* __restrict__ src, const int* __restrict__ dst) {
    int i = blockIdx.x * blockDim.x + threadIdx.x;
    if (i < NE) {
        atomicAdd(&g_deg[src[i]], 1);
        atomicAdd(&g_deg[NN + dst[i]], 1);
    }
}

// ---------------- exclusive scan of in-degrees -> rowptr, cursor ----------------
__global__ void __launch_bounds__(1024) k_scan() {
    __shared__ int sblk[1024];
    const int t = threadIdx.x;
    const int CH = (NN + 1023) / 1024;   // 98
    int lo = min(t * CH, NN);
    int hi = min(lo + CH, NN);
    int s = 0;
    for (int i = lo; i < hi; i++) s += g_deg[NN + i];
    sblk[t] = s;
    __syncthreads();
    for (int off = 1; off < 1024; off <<= 1) {
        int u = (t >= off) ? sblk[t - off] : 0;
        __syncthreads();
        sblk[t] += u;
        __syncthreads();
    }
    int run = (t > 0) ? sblk[t - 1] : 0;
    for (int i = lo; i < hi; i++) {
        g_rowptr[i] = run;
        g_cursor[i] = run;
        run += g_deg[NN + i];
    }
    if (t == 1023) g_rowptr[NN] = sblk[1023];
}

// ---------------- fill CSR ----------------
__global__ void k_fill(const int* __restrict__ src, const int* __restrict__ dst) {
    int e = blockIdx.x * blockDim.x + threadIdx.x;
    if (e < NE) {
        int d = dst[e];
        int pos = atomicAdd(&g_cursor[d], 1);
        g_col[pos] = src[e];
    }
}

// ---------------- layer-1 GEMM: h1 = (x @ W1) * norm_src ----------------
// Block tile 256 nodes x 64 feats; 256 threads; each thread 8 nodes x 8 feats.
__global__ void __launch_bounds__(256) k_gemm1(const float* __restrict__ x,
                                               const float* __restrict__ W1) {
    __shared__ __align__(16) float Xs[16][256];  // [k][node]  16KB
    __shared__ __align__(16) float Ws[16][64];   // [k][feat]  4KB

    const int tid = threadIdx.x;
    const int tx = tid & 7;     // feat group (8 feats)
    const int ty = tid >> 3;    // node group (8 nodes), 0..31
    const int n0 = blockIdx.x * 256;

    unsigned long long accp[8][4];
    #pragma unroll
    for (int i = 0; i < 8; i++)
        #pragma unroll
        for (int j = 0; j < 4; j++) accp[i][j] = 0ull;

    for (int kc = 0; kc < NF / 16; kc++) {
        __syncthreads();
        #pragma unroll
        for (int it = 0; it < 4; it++) {
            int i = tid + it * 256;          // 0..1023
            int nl = i >> 2, f4 = i & 3;
            int n = n0 + nl;
            float4 v = make_float4(0.f, 0.f, 0.f, 0.f);
            if (n < NN) v = *(const float4*)&x[(size_t)n * NF + kc * 16 + f4 * 4];
            Xs[f4 * 4 + 0][nl] = v.x;
            Xs[f4 * 4 + 1][nl] = v.y;
            Xs[f4 * 4 + 2][nl] = v.z;
            Xs[f4 * 4 + 3][nl] = v.w;
        }
        {
            int k = tid >> 4, f4 = tid & 15;
            *(float4*)&Ws[k][f4 * 4] =
                *(const float4*)&W1[(size_t)(kc * 16 + k) * NH + f4 * 4];
        }
        __syncthreads();

        #pragma unroll
        for (int kk = 0; kk < 16; kk++) {
            float4 a0 = *(const float4*)&Xs[kk][ty * 8];
            float4 a1 = *(const float4*)&Xs[kk][ty * 8 + 4];
            ulonglong2 w0 = *(const ulonglong2*)&Ws[kk][tx * 8];
            ulonglong2 w1 = *(const ulonglong2*)&Ws[kk][tx * 8 + 4];
            unsigned long long bp[4] = {w0.x, w0.y, w1.x, w1.y};
            float av[8] = {a0.x, a0.y, a0.z, a0.w, a1.x, a1.y, a1.z, a1.w};
            #pragma unroll
            for (int i = 0; i < 8; i++) {
                unsigned long long ad;
                asm("mov.b64 %0, {%1, %1};" : "=l"(ad) : "f"(av[i]));
                #pragma unroll
                for (int jj = 0; jj < 4; jj++)
                    asm("fma.rn.f32x2 %0, %1, %2, %0;"
                        : "+l"(accp[i][jj]) : "l"(ad), "l"(bp[jj]));
            }
        }
    }

    #pragma unroll
    for (int i = 0; i < 8; i++) {
        int n = n0 + ty * 8 + i;
        if (n < NN) {
            float s = rsqrtf((float)max(g_deg[n], 1));   // norm_src
            float o[8];
            #pragma unroll
            for (int jj = 0; jj < 4; jj++) {
                float lo, hi;
                asm("mov.b64 {%0, %1}, %2;" : "=f"(lo), "=f"(hi) : "l"(accp[i][jj]));
                o[2 * jj] = lo * s;
                o[2 * jj + 1] = hi * s;
            }
            *(float4*)&g_h1[(size_t)n * NH + tx * 8] = make_float4(o[0], o[1], o[2], o[3]);
            *(float4*)&g_h1[(size_t)n * NH + tx * 8 + 4] = make_float4(o[4], o[5], o[6], o[7]);
        }
    }
}

// ---------------- layer-1 gather: r = relu(sum_{e->n} h1[src] * nd + b1) ----------------
// 8 lanes per node, each owns 8 feats; direct broadcast col loads, unroll 4.
__global__ void __launch_bounds__(256) k_gather1(const float* __restrict__ b1) {
    const int g = blockIdx.x * 32 + (threadIdx.x >> 3);
    const int lane = threadIdx.x & 7;

    const int s0 = g_rowptr[g];
    const int s1 = g_rowptr[g + 1];
    unsigned long long acc[4] = {0ull, 0ull, 0ull, 0ull};

    int j = s0;
    for (; j + 4 <= s1; j += 4) {
        int c0 = __ldg(&g_col[j + 0]);
        int c1 = __ldg(&g_col[j + 1]);
        int c2 = __ldg(&g_col[j + 2]);
        int c3 = __ldg(&g_col[j + 3]);
        const ulonglong2* p0 = (const ulonglong2*)&g_h1[(size_t)c0 * NH + lane * 8];
        const ulonglong2* p1 = (const ulonglong2*)&g_h1[(size_t)c1 * NH + lane * 8];
        const ulonglong2* p2 = (const ulonglong2*)&g_h1[(size_t)c2 * NH + lane * 8];
        const ulonglong2* p3 = (const ulonglong2*)&g_h1[(size_t)c3 * NH + lane * 8];
        ulonglong2 a0 = p0[0], b0 = p0[1];
        ulonglong2 a1 = p1[0], b1v = p1[1];
        ulonglong2 a2 = p2[0], b2v = p2[1];
        ulonglong2 a3 = p3[0], b3v = p3[1];
        ADD2(acc[0], a0.x); ADD2(acc[1], a0.y); ADD2(acc[2], b0.x); ADD2(acc[3], b0.y);
        ADD2(acc[0], a1.x); ADD2(acc[1], a1.y); ADD2(acc[2], b1v.x); ADD2(acc[3], b1v.y);
        ADD2(acc[0], a2.x); ADD2(acc[1], a2.y); ADD2(acc[2], b2v.x); ADD2(acc[3], b2v.y);
        ADD2(acc[0], a3.x); ADD2(acc[1], a3.y); ADD2(acc[2], b3v.x); ADD2(acc[3], b3v.y);
    }
    for (; j < s1; j++) {
        int c = __ldg(&g_col[j]);
        const ulonglong2* p = (const ulonglong2*)&g_h1[(size_t)c * NH + lane * 8];
        ulonglong2 a = p[0], b = p[1];
        ADD2(acc[0], a.x); ADD2(acc[1], a.y); ADD2(acc[2], b.x); ADD2(acc[3], b.y);
    }

    float nd = rsqrtf((float)max(s1 - s0, 1));   // norm_dst
    float av[8];
    #pragma unroll
    for (int q = 0; q < 4; q++) {
        float lo, hi;
        asm("mov.b64 {%0, %1}, %2;" : "=f"(lo), "=f"(hi) : "l"(acc[q]));
        av[2 * q] = lo;
        av[2 * q + 1] = hi;
    }
    float4 bb0 = *(const float4*)&b1[lane * 8];
    float4 bb1 = *(const float4*)&b1[lane * 8 + 4];
    float bv[8] = {bb0.x, bb0.y, bb0.z, bb0.w, bb1.x, bb1.y, bb1.z, bb1.w};
    float r[8];
    #pragma unroll
    for (int q = 0; q < 8; q++) r[q] = fmaxf(fmaf(av[q], nd, bv[q]), 0.f);
    *(float4*)&g_r[(size_t)g * NH + lane * 8] = make_float4(r[0], r[1], r[2], r[3]);
    *(float4*)&g_r[(size_t)g * NH + lane * 8 + 4] = make_float4(r[4], r[5], r[6], r[7]);
}

// ---------------- hidden GEMM: h2 = (r @ W2) * norm_src ----------------
__global__ void __launch_bounds__(256) k_hidden(const float* __restrict__ W2) {
    __shared__ __align__(16) float R[16][NH + 4];
    __shared__ __align__(16) float W2s[NH * NC];

    const int n0 = blockIdx.x * 16;
    const int tid = threadIdx.x;

    *(float4*)&W2s[tid * 4] = *(const float4*)&W2[tid * 4];
    {
        int i = tid * 4;
        int nl = i >> 6;
        int k = i & 63;
        float4 v = *(const float4*)&g_r[(size_t)(n0 + nl) * NH + k];
        R[nl][k + 0] = v.x;
        R[nl][k + 1] = v.y;
        R[nl][k + 2] = v.z;
        R[nl][k + 3] = v.w;
    }
    __syncthreads();

    const int nl = tid >> 4;
    const int cl = tid & 15;
    const int n = n0 + nl;
    float acc = 0.f;
    #pragma unroll
    for (int k = 0; k < NH; k++)
        acc = fmaf(R[nl][k], W2s[k * NC + cl], acc);
    g_h2[(size_t)n * NC + cl] = acc * rsqrtf((float)max(g_deg[n], 1));
}

// ---------------- layer-2 gather + log_softmax fused ----------------
// 2 lanes per node, each owns 8 classes; direct col loads, unroll 4.
__global__ void __launch_bounds__(256) k_gather2(const float* __restrict__ b2,
                                                 float* __restrict__ out) {
    const int g = blockIdx.x * 128 + (threadIdx.x >> 1);
    const int lane = threadIdx.x & 1;
    const unsigned pb = (threadIdx.x & 31) & ~1u;
    const unsigned mask = 3u << pb;
    if (g >= NN) return;

    const int s0 = g_rowptr[g];
    const int s1 = g_rowptr[g + 1];
    unsigned long long acc[4] = {0ull, 0ull, 0ull, 0ull};

    int j = s0;
    for (; j + 4 <= s1; j += 4) {
        int c0 = __ldg(&g_col[j + 0]);
        int c1 = __ldg(&g_col[j + 1]);
        int c2 = __ldg(&g_col[j + 2]);
        int c3 = __ldg(&g_col[j + 3]);
        const ulonglong2* p0 = (const ulonglong2*)&g_h2[(size_t)c0 * NC + lane * 8];
        const ulonglong2* p1 = (const ulonglong2*)&g_h2[(size_t)c1 * NC + lane * 8];
        const ulonglong2* p2 = (const ulonglong2*)&g_h2[(size_t)c2 * NC + lane * 8];
        const ulonglong2* p3 = (const ulonglong2*)&g_h2[(size_t)c3 * NC + lane * 8];
        ulonglong2 a0 = p0[0], b0 = p0[1];
        ulonglong2 a1 = p1[0], b1v = p1[1];
        ulonglong2 a2 = p2[0], b2v = p2[1];
        ulonglong2 a3 = p3[0], b3v = p3[1];
        ADD2(acc[0], a0.x); ADD2(acc[1], a0.y); ADD2(acc[2], b0.x); ADD2(acc[3], b0.y);
        ADD2(acc[0], a1.x); ADD2(acc[1], a1.y); ADD2(acc[2], b1v.x); ADD2(acc[3], b1v.y);
        ADD2(acc[0], a2.x); ADD2(acc[1], a2.y); ADD2(acc[2], b2v.x); ADD2(acc[3], b2v.y);
        ADD2(acc[0], a3.x); ADD2(acc[1], a3.y); ADD2(acc[2], b3v.x); ADD2(acc[3], b3v.y);
    }
    for (; j < s1; j++) {
        int c = __ldg(&g_col[j]);
        const ulonglong2* p = (const ulonglong2*)&g_h2[(size_t)c * NC + lane * 8];
        ulonglong2 a = p[0], b = p[1];
        ADD2(acc[0], a.x); ADD2(acc[1], a.y); ADD2(acc[2], b.x); ADD2(acc[3], b.y);
    }

    float nd = rsqrtf((float)max(s1 - s0, 1));
    float av[8];
    #pragma unroll
    for (int q = 0; q < 4; q++) {
        float lo, hi;
        asm("mov.b64 {%0, %1}, %2;" : "=f"(lo), "=f"(hi) : "l"(acc[q]));
        av[2 * q] = lo;
        av[2 * q + 1] = hi;
    }
    float4 bb0 = *(const float4*)&b2[lane * 8];
    float4 bb1 = *(const float4*)&b2[lane * 8 + 4];
    float bv[8] = {bb0.x, bb0.y, bb0.z, bb0.w, bb1.x, bb1.y, bb1.z, bb1.w};
    float v[8];
    #pragma unroll
    for (int q = 0; q < 8; q++) v[q] = fmaf(av[q], nd, bv[q]);

    float mloc = v[0];
    #pragma unroll
    for (int q = 1; q < 8; q++) mloc = fmaxf(mloc, v[q]);
    float mo = __shfl_xor_sync(mask, mloc, 1, 2);
    float mx = fmaxf(mloc, mo);

    float sl = 0.f;
    #pragma unroll
    for (int q = 0; q < 8; q++) sl += __expf(v[q] - mx);
    float so = __shfl_xor_sync(mask, sl, 1, 2);
    float l = mx + __logf(sl + so);

    *(float4*)&out[(size_t)g * NC + lane * 8] =
        make_float4(v[0] - l, v[1] - l, v[2] - l, v[3] - l);
    *(float4*)&out[(size_t)g * NC + lane * 8 + 4] =
        make_float4(v[4] - l, v[5] - l, v[6] - l, v[7] - l);
}

// ---------------- launch ----------------
extern "C" void kernel_launch(void* const* d_in, const int* in_sizes, int n_in,
                              void* d_out, int out_size) {
    const float* x   = (const float*)d_in[0];
    const int*   src = (const int*)d_in[1];
    const int*   dst = (const int*)d_in[2];
    const float* W1  = (const float*)d_in[3];
    const float* b1  = (const float*)d_in[4];
    const float* W2  = (const float*)d_in[5];
    const float* b2  = (const float*)d_in[6];
    float* out = (float*)d_out;

    void* pdeg;
    cudaGetSymbolAddress(&pdeg, g_deg);
    cudaMemsetAsync(pdeg, 0, (size_t)2 * NN * sizeof(int));      // launch 0

    k_hist<<<(NE + 255) / 256, 256>>>(src, dst);                 // 1
    k_scan<<<1, 1024>>>();                                       // 2
    k_fill<<<(NE + 255) / 256, 256>>>(src, dst);                 // 3
    k_gemm1<<<(NN + 255) / 256, 256>>>(x, W1);                   // 4
    k_gather1<<<NN / 32, 256>>>(b1);                             // 5  <- profiled
    k_hidden<<<NN / 16, 256>>>(W2);                              // 6
    k_gather2<<<(NN + 127) / 128, 256>>>(b2, out);               // 7
}

// round 6
// speedup vs baseline: 2.1144x; 1.9087x over previous
#include <cuda_runtime.h>

#define NN 100000
#define NE 1600000
#define NF 128
#define NH 64
#define NC 16

// ---------------- scratch (static device globals) ----------------
__device__ int   g_deg[2 * NN];             // [0,NN): out-degree, [NN,2NN): in-degree
__device__ int   g_part[256];               // scan partials (196 used)
__device__ int   g_rowptr[NN + 1];
__device__ int   g_cursor[NN];
__device__ int   g_col[NE];                 // src node per CSR slot
__device__ float g_h1[(size_t)NN * NH];     // (x@W1)*norm_src
__device__ float g_r[(size_t)NN * NH];      // relu(agg1*nd + b1)
__device__ float g_h2[(size_t)NN * NC];     // (r@W2)*norm_src

#define ADD2(acc, v) asm("add.rn.f32x2 %0, %0, %1;" : "+l"(acc) : "l"(v))
#define CP16(dst, src, sz) \
    asm volatile("cp.async.cg.shared.global [%0], [%1], 16, %2;" \
                 :: "r"(dst), "l"(src), "r"(sz))

__device__ __forceinline__ unsigned smem_u32(const void* p) {
    return (unsigned)__cvta_generic_to_shared(p);
}

// ---------------- in-degree histogram ----------------
__global__ void k_hist(const int* __restrict__ dst) {
    int i = blockIdx.x * blockDim.x + threadIdx.x;
    if (i < NE) atomicAdd(&g_deg[NN + dst[i]], 1);
}

// ---------------- scan phase A: 196 blocks x 512 nodes -> block sums ----------------
__global__ void __launch_bounds__(256) k_scanA() {
    __shared__ int sh[256];
    const int t = threadIdx.x;
    int i0 = blockIdx.x * 512 + 2 * t;
    int s = 0;
    if (i0 < NN) s += g_deg[NN + i0];
    if (i0 + 1 < NN) s += g_deg[NN + i0 + 1];
    sh[t] = s;
    __syncthreads();
    for (int off = 128; off > 0; off >>= 1) {
        if (t < off) sh[t] += sh[t + off];
        __syncthreads();
    }
    if (t == 0) g_part[blockIdx.x] = sh[0];
    if (t == 1 && blockIdx.x == 0) g_rowptr[NN] = NE;
}

// ---------------- scan phase C: every block scans partials + local scan ----------------
__global__ void __launch_bounds__(256) k_scanC() {
    __shared__ int part[256];
    __shared__ int loc[256];
    const int t = threadIdx.x;
    const int b = blockIdx.x;

    part[t] = (t < 196) ? g_part[t] : 0;
    __syncthreads();
    for (int off = 1; off < 256; off <<= 1) {
        int u = (t >= off) ? part[t - off] : 0;
        __syncthreads();
        part[t] += u;
        __syncthreads();
    }
    int offset = (b > 0) ? part[b - 1] : 0;

    int i0 = b * 512 + 2 * t;
    int d0 = (i0 < NN) ? g_deg[NN + i0] : 0;
    int d1 = (i0 + 1 < NN) ? g_deg[NN + i0 + 1] : 0;
    loc[t] = d0 + d1;
    __syncthreads();
    for (int off = 1; off < 256; off <<= 1) {
        int u = (t >= off) ? loc[t - off] : 0;
        __syncthreads();
        loc[t] += u;
        __syncthreads();
    }
    int excl = offset + ((t > 0) ? loc[t - 1] : 0);
    if (i0 < NN)     { g_rowptr[i0] = excl;          g_cursor[i0] = excl; }
    if (i0 + 1 < NN) { g_rowptr[i0 + 1] = excl + d0; g_cursor[i0 + 1] = excl + d0; }
}

// ---------------- fill CSR + out-degree ----------------
__global__ void k_fill(const int* __restrict__ src, const int* __restrict__ dst) {
    int e = blockIdx.x * blockDim.x + threadIdx.x;
    if (e < NE) {
        int d = dst[e];
        int s = src[e];
        int pos = atomicAdd(&g_cursor[d], 1);
        g_col[pos] = s;
        atomicAdd(&g_deg[s], 1);
    }
}

// ---------------- layer-1 GEMM: h1 = (x @ W1) * norm_src ----------------
// 256 nodes x 64 feats per block; cp.async double-buffered; 8x8/thread f32x2.
__global__ void __launch_bounds__(256) k_gemm1(const float* __restrict__ x,
                                               const float* __restrict__ W1) {
    __shared__ __align__(16) float Xs[2][256][20];  // node-major, 80B stride: 40KB
    __shared__ __align__(16) float Ws[2][16][64];   // 8KB  (total 48KB exactly)

    const int tid = threadIdx.x;
    const int tx = tid & 7;     // feat group (8 feats)
    const int ty = tid >> 3;    // node group (8 nodes), 0..31
    const int n0 = blockIdx.x * 256;

    // per-thread cp.async coordinates
    const int xk = tid & 3;            // which 16B chunk of the 16-k slice
    const int wkk = tid >> 4, wf4 = tid & 15;

    unsigned long long accp[8][4];
    #pragma unroll
    for (int i = 0; i < 8; i++)
        #pragma unroll
        for (int j = 0; j < 4; j++) accp[i][j] = 0ull;

    // issue chunk kc into buffer kc&1
    auto issue = [&](int kc) {
        int buf = kc & 1;
        #pragma unroll
        for (int it = 0; it < 4; it++) {
            int i = tid + it * 256;          // 0..1023
            int nl = i >> 2, f4 = i & 3;
            int n = n0 + nl;
            unsigned d = smem_u32(&Xs[buf][nl][f4 * 4]);
            const float* s = &x[(size_t)n * NF + kc * 16 + f4 * 4];
            CP16(d, s, (n < NN) ? 16 : 0);
        }
        unsigned dw = smem_u32(&Ws[buf][wkk][wf4 * 4]);
        const float* sw = &W1[(size_t)(kc * 16 + wkk) * NH + wf4 * 4];
        CP16(dw, sw, 16);
        asm volatile("cp.async.commit_group;");
    };

    issue(0);
    for (int kc = 0; kc < NF / 16; kc++) {
        if (kc + 1 < NF / 16) {
            issue(kc + 1);
            asm volatile("cp.async.wait_group 1;");
        } else {
            asm volatile("cp.async.wait_group 0;");
        }
        __syncthreads();
        const int buf = kc & 1;

        #pragma unroll
        for (int kk = 0; kk < 16; kk++) {
            float av[8];
            #pragma unroll
            for (int i = 0; i < 8; i++) av[i] = Xs[buf][ty * 8 + i][kk];
            ulonglong2 w0 = *(const ulonglong2*)&Ws[buf][kk][tx * 8];
            ulonglong2 w1 = *(const ulonglong2*)&Ws[buf][kk][tx * 8 + 4];
            unsigned long long bp[4] = {w0.x, w0.y, w1.x, w1.y};
            #pragma unroll
            for (int i = 0; i < 8; i++) {
                unsigned long long ad;
                asm("mov.b64 %0, {%1, %1};" : "=l"(ad) : "f"(av[i]));
                #pragma unroll
                for (int jj = 0; jj < 4; jj++)
                    asm("fma.rn.f32x2 %0, %1, %2, %0;"
                        : "+l"(accp[i][jj]) : "l"(ad), "l"(bp[jj]));
            }
        }
        __syncthreads();   // buffer consumed; safe to refill on next-next issue
    }

    #pragma unroll
    for (int i = 0; i < 8; i++) {
        int n = n0 + ty * 8 + i;
        if (n < NN) {
            float s = rsqrtf((float)max(g_deg[n], 1));   // norm_src
            float o[8];
            #pragma unroll
            for (int jj = 0; jj < 4; jj++) {
                float lo, hi;
                asm("mov.b64 {%0, %1}, %2;" : "=f"(lo), "=f"(hi) : "l"(accp[i][jj]));
                o[2 * jj] = lo * s;
                o[2 * jj + 1] = hi * s;
            }
            *(float4*)&g_h1[(size_t)n * NH + tx * 8] = make_float4(o[0], o[1], o[2], o[3]);
            *(float4*)&g_h1[(size_t)n * NH + tx * 8 + 4] = make_float4(o[4], o[5], o[6], o[7]);
        }
    }
}

// ---------------- layer-1 gather: r = relu(sum h1[src] * nd + b1) ----------------
// 16 lanes/node, 1 float4 each; unroll 8 -> 8 LDG.128 in flight per lane.
__global__ void __launch_bounds__(256) k_gather1(const float* __restrict__ b1) {
    const int g = blockIdx.x * 16 + (threadIdx.x >> 4);
    const int lane = threadIdx.x & 15;

    const int s0 = g_rowptr[g];
    const int s1 = g_rowptr[g + 1];
    unsigned long long acc0 = 0ull, acc1 = 0ull;

    int j = s0;
    for (; j + 8 <= s1; j += 8) {
        int c[8];
        #pragma unroll
        for (int q = 0; q < 8; q++) c[q] = __ldg(&g_col[j + q]);
        #pragma unroll
        for (int q = 0; q < 8; q++) {
            ulonglong2 v = *(const ulonglong2*)&g_h1[(size_t)c[q] * NH + lane * 4];
            ADD2(acc0, v.x);
            ADD2(acc1, v.y);
        }
    }
    for (; j < s1; j++) {
        int c = __ldg(&g_col[j]);
        ulonglong2 v = *(const ulonglong2*)&g_h1[(size_t)c * NH + lane * 4];
        ADD2(acc0, v.x);
        ADD2(acc1, v.y);
    }

    float nd = rsqrtf((float)max(s1 - s0, 1));   // norm_dst
    float a0, a1, a2, a3;
    asm("mov.b64 {%0, %1}, %2;" : "=f"(a0), "=f"(a1) : "l"(acc0));
    asm("mov.b64 {%0, %1}, %2;" : "=f"(a2), "=f"(a3) : "l"(acc1));
    float4 bb = *(const float4*)&b1[lane * 4];
    float4 r;
    r.x = fmaxf(fmaf(a0, nd, bb.x), 0.f);
    r.y = fmaxf(fmaf(a1, nd, bb.y), 0.f);
    r.z = fmaxf(fmaf(a2, nd, bb.z), 0.f);
    r.w = fmaxf(fmaf(a3, nd, bb.w), 0.f);
    *(float4*)&g_r[(size_t)g * NH + lane * 4] = r;
}

// ---------------- hidden GEMM: h2 = (r @ W2) * norm_src ----------------
__global__ void __launch_bounds__(256) k_hidden(const float* __restrict__ W2) {
    __shared__ __align__(16) float R[16][NH + 4];
    __shared__ __align__(16) float W2s[NH * NC];

    const int n0 = blockIdx.x * 16;
    const int tid = threadIdx.x;

    *(float4*)&W2s[tid * 4] = *(const float4*)&W2[tid * 4];
    {
        int i = tid * 4;
        int nl = i >> 6;
        int k = i & 63;
        float4 v = *(const float4*)&g_r[(size_t)(n0 + nl) * NH + k];
        R[nl][k + 0] = v.x;
        R[nl][k + 1] = v.y;
        R[nl][k + 2] = v.z;
        R[nl][k + 3] = v.w;
    }
    __syncthreads();

    const int nl = tid >> 4;
    const int cl = tid & 15;
    const int n = n0 + nl;
    float acc = 0.f;
    #pragma unroll
    for (int k = 0; k < NH; k++)
        acc = fmaf(R[nl][k], W2s[k * NC + cl], acc);
    g_h2[(size_t)n * NC + cl] = acc * rsqrtf((float)max(g_deg[n], 1));
}

// ---------------- layer-2 gather + log_softmax fused ----------------
// 4 lanes/node, 1 float4 (4 classes) each; unroll 8.
__global__ void __launch_bounds__(256) k_gather2(const float* __restrict__ b2,
                                                 float* __restrict__ out) {
    int g0 = blockIdx.x * 64 + (threadIdx.x >> 2);
    const bool valid = (g0 < NN);
    const int g = valid ? g0 : (NN - 1);
    const int lane = threadIdx.x & 3;

    const int s0 = g_rowptr[g];
    const int s1 = g_rowptr[g + 1];
    unsigned long long acc0 = 0ull, acc1 = 0ull;

    int j = s0;
    for (; j + 8 <= s1; j += 8) {
        int c[8];
        #pragma unroll
        for (int q = 0; q < 8; q++) c[q] = __ldg(&g_col[j + q]);
        #pragma unroll
        for (int q = 0; q < 8; q++) {
            ulonglong2 v = *(const ulonglong2*)&g_h2[(size_t)c[q] * NC + lane * 4];
            ADD2(acc0, v.x);
            ADD2(acc1, v.y);
        }
    }
    for (; j < s1; j++) {
        int c = __ldg(&g_col[j]);
        ulonglong2 v = *(const ulonglong2*)&g_h2[(size_t)c * NC + lane * 4];
        ADD2(acc0, v.x);
        ADD2(acc1, v.y);
    }

    float nd = rsqrtf((float)max(s1 - s0, 1));
    float v[4];
    asm("mov.b64 {%0, %1}, %2;" : "=f"(v[0]), "=f"(v[1]) : "l"(acc0));
    asm("mov.b64 {%0, %1}, %2;" : "=f"(v[2]), "=f"(v[3]) : "l"(acc1));
    float4 bb = *(const float4*)&b2[lane * 4];
    v[0] = fmaf(v[0], nd, bb.x);
    v[1] = fmaf(v[1], nd, bb.y);
    v[2] = fmaf(v[2], nd, bb.z);
    v[3] = fmaf(v[3], nd, bb.w);

    float mloc = fmaxf(fmaxf(v[0], v[1]), fmaxf(v[2], v[3]));
    mloc = fmaxf(mloc, __shfl_xor_sync(0xFFFFFFFFu, mloc, 1, 4));
    mloc = fmaxf(mloc, __shfl_xor_sync(0xFFFFFFFFu, mloc, 2, 4));

    float sl = __expf(v[0] - mloc) + __expf(v[1] - mloc) +
               __expf(v[2] - mloc) + __expf(v[3] - mloc);
    sl += __shfl_xor_sync(0xFFFFFFFFu, sl, 1, 4);
    sl += __shfl_xor_sync(0xFFFFFFFFu, sl, 2, 4);
    float l = mloc + __logf(sl);

    if (valid)
        *(float4*)&out[(size_t)g * NC + lane * 4] =
            make_float4(v[0] - l, v[1] - l, v[2] - l, v[3] - l);
}

// ---------------- launch ----------------
extern "C" void kernel_launch(void* const* d_in, const int* in_sizes, int n_in,
                              void* d_out, int out_size) {
    const float* x   = (const float*)d_in[0];
    const int*   src = (const int*)d_in[1];
    const int*   dst = (const int*)d_in[2];
    const float* W1  = (const float*)d_in[3];
    const float* b1  = (const float*)d_in[4];
    const float* W2  = (const float*)d_in[5];
    const float* b2  = (const float*)d_in[6];
    float* out = (float*)d_out;

    void* pdeg;
    cudaGetSymbolAddress(&pdeg, g_deg);
    cudaMemsetAsync(pdeg, 0, (size_t)2 * NN * sizeof(int));

    k_hist<<<(NE + 255) / 256, 256>>>(dst);
    k_scanA<<<196, 256>>>();
    k_scanC<<<196, 256>>>();
    k_fill<<<(NE + 255) / 256, 256>>>(src, dst);
    k_gemm1<<<(NN + 255) / 256, 256>>>(x, W1);
    k_gather1<<<NN / 16, 256>>>(b1);
    k_hidden<<<NN / 16, 256>>>(W2);
    k_gather2<<<(NN + 63) / 64, 256>>>(b2, out);
}